// round 7
// baseline (speedup 1.0000x reference)
#include <cuda_runtime.h>
#include <cuda_fp16.h>
#include <cstdint>

// VanillaRNN via warp-level HMMA, fp16 3-pass hi/lo split.
// R7: software-pipelined k-loop — LDSM fragments for kstep k+1 prefetched
// into a double buffer while kstep k's 12 MMAs issue. bias moved to smem
// to free the registers for the second fragment buffer.

#define BATCH 2048
#define SEQT  512
#define HDIM  256
#define NCOL  16
#define NBLK  128
#define NTHR  256
#define NSTEPS 510
#define SCALE   256.0f
#define INVSCALE 0.00390625f

// smem byte offsets
#define SM_W    0          // init: W_hi staging; steady: W_lo*2^8 [256 rows][512B]
#define SM_B    131072     // h buffers: [buf0 hi 8K | lo 8K][buf1 hi 8K | lo 8K]
#define SM_XR   163840     // x ring: 2 slots x 16 f32
#define SM_BIAS 163968     // bias [16][256] f32
#define SM_TOTAL 180352

__device__ __forceinline__ uint32_t s2u(const void* p) {
    uint32_t a;
    asm("{ .reg .u64 t; cvta.to.shared.u64 t, %1; cvt.u32.u64 %0, t; }" : "=r"(a) : "l"(p));
    return a;
}

#define LDSM4(r, a)                                                               \
    asm volatile("ldmatrix.sync.aligned.m8n8.x4.shared.b16 {%0,%1,%2,%3}, [%4];"  \
                 : "=r"((r)[0]), "=r"((r)[1]), "=r"((r)[2]), "=r"((r)[3])         \
                 : "r"(a))

__device__ __forceinline__ void mma_f32(float* d, const uint32_t* a,
                                        uint32_t b0, uint32_t b1) {
    asm volatile("mma.sync.aligned.m16n8k16.row.col.f32.f16.f16.f32 "
                 "{%0,%1,%2,%3}, {%4,%5,%6,%7}, {%8,%9}, {%0,%1,%2,%3};"
                 : "+f"(d[0]), "+f"(d[1]), "+f"(d[2]), "+f"(d[3])
                 : "r"(a[0]), "r"(a[1]), "r"(a[2]), "r"(a[3]), "r"(b0), "r"(b1));
}
__device__ __forceinline__ void mma_f16(uint32_t* d, const uint32_t* a,
                                        uint32_t b0, uint32_t b1) {
    asm volatile("mma.sync.aligned.m16n8k16.row.col.f16.f16.f16.f16 "
                 "{%0,%1}, {%2,%3,%4,%5}, {%6,%7}, {%0,%1};"
                 : "+r"(d[0]), "+r"(d[1])
                 : "r"(a[0]), "r"(a[1]), "r"(a[2]), "r"(a[3]), "r"(b0), "r"(b1));
}

__device__ __forceinline__ float tanh_fast(float v) {
    float e = __expf(2.0f * v);
    return 1.0f - __fdividef(2.0f, e + 1.0f);
}

__global__ void __launch_bounds__(NTHR, 1) VanillaRNN_54984171323420_kernel(
    const float* __restrict__ x,    // [2048, 512]
    const float* __restrict__ Whx,  // [256, 1]
    const float* __restrict__ Whh,  // [256, 256]
    const float* __restrict__ Wph,  // [10, 256]
    const float* __restrict__ bh,   // [256, 2048]
    const float* __restrict__ bp,   // [10, 2048]
    float* __restrict__ out)        // [2048, 10]
{
    extern __shared__ char smc[];
    const uint32_t sb = s2u(smc);
    const int tid = threadIdx.x;
    const int w = tid >> 5;          // warp 0..7 -> m rows [32w, 32w+32)
    const int l = tid & 31;
    const int lq = l >> 2;
    const int lr = (l & 3) * 2;
    const int lx = l >> 4;
    const int l7 = l & 7;
    const int m0 = 32 * w;
    const int j0 = blockIdx.x * NCOL;

    // ---------------- stage W_hi into smem (swizzled 512B rows) ----------------
    for (int idx = tid; idx < HDIM * HDIM; idx += NTHR) {
        int m = idx >> 8, k = idx & 255;
        __half hi = __float2half_rn(Whh[idx]);
        uint32_t ch = (uint32_t)(((k >> 3) ^ (m & 7)) << 4);
        *(__half*)(smc + SM_W + m * 512 + ch + (k & 7) * 2) = hi;
    }
    float xn1 = 0.0f;
    if (tid < NCOL) {
        const float* xr = x + (j0 + tid) * SEQT;
        *(float*)(smc + SM_XR + 64 + tid * 4) = xr[0];
        xn1 = xr[1];
    }
    __syncthreads();

    // ---------------- A_hi fragments -> registers (loop-invariant, 128 regs) ----
    const uint32_t rowAL0 = sb + SM_W + (uint32_t)(m0 + (l & 15)) * 512;
    const uint32_t rowAL1 = rowAL0 + 16 * 512;
    uint32_t ahi0[16][4], ahi1[16][4];
#pragma unroll
    for (int ks = 0; ks < 16; ks++) {
        const uint32_t ch = (uint32_t)(((2 * ks + lx) ^ l7) << 4);
        LDSM4(ahi0[ks], rowAL0 + ch);
        LDSM4(ahi1[ks], rowAL1 + ch);
    }
    __syncthreads();

    // ---------------- overwrite staging with W_lo * 2^8 ----------------
    for (int idx = tid; idx < HDIM * HDIM; idx += NTHR) {
        int m = idx >> 8, k = idx & 255;
        float wv = Whh[idx];
        __half hi = __float2half_rn(wv);
        __half lo = __float2half_rn((wv - __half2float(hi)) * SCALE);
        uint32_t ch = (uint32_t)(((k >> 3) ^ (m & 7)) << 4);
        *(__half*)(smc + SM_W + m * 512 + ch + (k & 7) * 2) = lo;
    }

    // ---------------- bias -> smem [q][tid]; Whx fragments in regs ----------------
    float wx[2][2];
#pragma unroll
    for (int tm = 0; tm < 2; tm++) {
        wx[tm][0] = Whx[m0 + 16 * tm + lq];
        wx[tm][1] = Whx[m0 + 16 * tm + lq + 8];
#pragma unroll
        for (int tn = 0; tn < 2; tn++)
#pragma unroll
            for (int e = 0; e < 4; e++) {
                int m = m0 + 16 * tm + lq + ((e >> 1) ? 8 : 0);
                int n = 8 * tn + lr + (e & 1);
                int q = tm * 8 + tn * 4 + e;
                *(float*)(smc + SM_BIAS + (q * 256 + tid) * 4) = bh[m * BATCH + j0 + n];
            }
    }

    // ---------------- prologue: h1 = tanh(b_h + Whx*x_0) -> buf0 ----------------
#pragma unroll
    for (int tm = 0; tm < 2; tm++)
#pragma unroll
        for (int tn = 0; tn < 2; tn++)
#pragma unroll
            for (int e = 0; e < 4; e++) {
                int n = 8 * tn + lr + (e & 1);
                int mh = e >> 1;
                int m = m0 + 16 * tm + lq + (mh ? 8 : 0);
                int q = tm * 8 + tn * 4 + e;
                float bv = *(const float*)(smc + SM_BIAS + (q * 256 + tid) * 4);
                float xv = *(const float*)(smc + SM_XR + 64 + n * 4);
                float h = tanh_fast(bv + wx[tm][mh] * xv);
                __half hi = __float2half_rn(h);
                __half lo = __float2half_rn((h - __half2float(hi)) * SCALE);
                uint32_t off = (uint32_t)n * 512 + ((((uint32_t)m >> 3) ^ (n & 7)) << 4) + (m & 7) * 2;
                *(__half*)(smc + SM_B + off) = hi;
                *(__half*)(smc + SM_B + 8192 + off) = lo;
            }
    if (tid < NCOL) *(float*)(smc + SM_XR + tid * 4) = xn1;  // slot0 <- x_1
    __syncthreads();

    const uint32_t rowBb = sb + SM_B + (uint32_t)(l & 15) * 512;

    // ================= recurrence: 510 HMMA steps, 1 bar/step =================
#pragma unroll 2
    for (int it = 0; it < NSTEPS; it++) {
        const int p = it & 1;                 // read buf p, write buf 1-p
        float xnext = 0.0f;
        if (tid < NCOL) xnext = x[(j0 + tid) * SEQT + it + 2];

        const uint32_t rowB = rowBb + (uint32_t)p * 16384;

        float d32[16];
#pragma unroll
        for (int q = 0; q < 16; q++)
            d32[q] = *(const float*)(smc + SM_BIAS + (q * 256 + tid) * 4);
        uint32_t dlo[4][2];
#pragma unroll
        for (int q = 0; q < 4; q++) { dlo[q][0] = 0u; dlo[q][1] = 0u; }

        // ---- software-pipelined k-loop: prefetch ks+1 while ks computes ----
        uint32_t bh4[2][4], bl4[2][4], al0[2][4], al1[2][4];
        {
            const uint32_t ch = (uint32_t)((lx ^ l7) << 4);
            LDSM4(bh4[0], rowB + ch);
            LDSM4(bl4[0], rowB + 8192 + ch);
            LDSM4(al0[0], rowAL0 + ch);
            LDSM4(al1[0], rowAL1 + ch);
        }
#pragma unroll
        for (int ks = 0; ks < 16; ks++) {
            const int cb = ks & 1, nb = cb ^ 1;
            if (ks < 15) {
                const uint32_t ch = (uint32_t)(((2 * (ks + 1) + lx) ^ l7) << 4);
                LDSM4(bh4[nb], rowB + ch);
                LDSM4(bl4[nb], rowB + 8192 + ch);
                LDSM4(al0[nb], rowAL0 + ch);
                LDSM4(al1[nb], rowAL1 + ch);
            }
            // main pass: W_hi . h_hi  (f32 accum)
            mma_f32(&d32[0],  ahi0[ks], bh4[cb][0], bh4[cb][2]);
            mma_f32(&d32[4],  ahi0[ks], bh4[cb][1], bh4[cb][3]);
            mma_f32(&d32[8],  ahi1[ks], bh4[cb][0], bh4[cb][2]);
            mma_f32(&d32[12], ahi1[ks], bh4[cb][1], bh4[cb][3]);
            // correction passes (x 2^8): W_lo.h_hi + W_hi.h_lo  (f16 accum)
            mma_f16(dlo[0], al0[cb],  bh4[cb][0], bh4[cb][2]);
            mma_f16(dlo[0], ahi0[ks], bl4[cb][0], bl4[cb][2]);
            mma_f16(dlo[1], al0[cb],  bh4[cb][1], bh4[cb][3]);
            mma_f16(dlo[1], ahi0[ks], bl4[cb][1], bl4[cb][3]);
            mma_f16(dlo[2], al1[cb],  bh4[cb][0], bh4[cb][2]);
            mma_f16(dlo[2], ahi1[ks], bl4[cb][0], bl4[cb][2]);
            mma_f16(dlo[3], al1[cb],  bh4[cb][1], bh4[cb][3]);
            mma_f16(dlo[3], ahi1[ks], bl4[cb][1], bl4[cb][3]);
        }

        // ---- epilogue: h = tanh(d32 + dlo*2^-8 + Whx*x) -> buf 1-p ----
        const uint32_t xsl = (uint32_t)(SM_XR + p * 64);
        const uint32_t bufw = (uint32_t)(SM_B + (1 - p) * 16384);
#pragma unroll
        for (int tm = 0; tm < 2; tm++)
#pragma unroll
            for (int tn = 0; tn < 2; tn++) {
                float2 lo01 = __half22float2(*(__half2*)&dlo[tm * 2 + tn][0]);
                float2 lo23 = __half22float2(*(__half2*)&dlo[tm * 2 + tn][1]);
                float lov[4] = {lo01.x, lo01.y, lo23.x, lo23.y};
#pragma unroll
                for (int e = 0; e < 4; e++) {
                    int idx = tm * 8 + tn * 4 + e;
                    int n = 8 * tn + lr + (e & 1);
                    int mh = e >> 1;
                    int m = m0 + 16 * tm + lq + (mh ? 8 : 0);
                    float xv = *(const float*)(smc + xsl + n * 4);
                    float pre = fmaf(wx[tm][mh], xv, fmaf(lov[e], INVSCALE, d32[idx]));
                    float h = tanh_fast(pre);
                    __half hi = __float2half_rn(h);
                    __half lo = __float2half_rn((h - __half2float(hi)) * SCALE);
                    uint32_t off = (uint32_t)n * 512 + ((((uint32_t)m >> 3) ^ (n & 7)) << 4) + (m & 7) * 2;
                    *(__half*)(smc + bufw + off) = hi;
                    *(__half*)(smc + bufw + 8192 + off) = lo;
                }
            }
        if (tid < NCOL) *(float*)(smc + SM_XR + (1 - p) * 64 + tid * 4) = xnext;
        __syncthreads();
    }

    // ================= projection: out = Wph @ h + bp =================
    // final h lives in buf0 (it=509 wrote buf 1-p = 0)
    if (tid < 10 * NCOL) {
        const int c = tid >> 4, j = tid & 15;
        float s = bp[c * BATCH + j0 + j];
        const float* wr = Wph + c * HDIM;
#pragma unroll 8
        for (int k = 0; k < HDIM; k++) {
            uint32_t off = (uint32_t)j * 512 + ((((uint32_t)k >> 3) ^ (j & 7)) << 4) + (k & 7) * 2;
            float hv = __half2float(*(__half*)(smc + SM_B + off)) +
                       __half2float(*(__half*)(smc + SM_B + 8192 + off)) * INVSCALE;
            s = fmaf(wr[k], hv, s);
        }
        out[(j0 + j) * 10 + c] = s;
    }
}

extern "C" void kernel_launch(void* const* d_in, const int* in_sizes, int n_in,
                              void* d_out, int out_size) {
    const float* x   = (const float*)d_in[0];
    const float* Whx = (const float*)d_in[1];
    const float* Whh = (const float*)d_in[2];
    const float* Wph = (const float*)d_in[3];
    const float* bh  = (const float*)d_in[4];
    const float* bp  = (const float*)d_in[5];
    float* out = (float*)d_out;

    cudaFuncSetAttribute(VanillaRNN_54984171323420_kernel,
                         cudaFuncAttributeMaxDynamicSharedMemorySize, SM_TOTAL);
    VanillaRNN_54984171323420_kernel<<<NBLK, NTHR, SM_TOTAL>>>(
        x, Whx, Whh, Wph, bh, bp, out);
}

// round 9
// speedup vs baseline: 1.0028x; 1.0028x over previous
#include <cuda_runtime.h>
#include <cuda_fp16.h>
#include <cstdint>

// VanillaRNN via warp-level HMMA, fp16 3-pass hi/lo split.
// R9 = R8 with address-space fix: split f16 correction accumulators
// (12 indep MMA chains), bias in smem (generic-pointer loads), precomputed
// packed epilogue store offsets, ILP-restructured epilogue.

#define BATCH 2048
#define SEQT  512
#define HDIM  256
#define NCOL  16
#define NBLK  128
#define NTHR  256
#define NSTEPS 510
#define SCALE   256.0f
#define INVSCALE 0.00390625f

// smem byte offsets
#define SM_W    0          // init: W_hi staging; steady: W_lo*2^8 [256 rows][512B]
#define SM_B    131072     // h buffers: [buf0 hi 8K | lo 8K][buf1 hi 8K | lo 8K]
#define SM_XR   163840     // x ring: 2 slots x 16 f32
#define SM_BIAS 163968     // bias [16][256] f32
#define SM_TOTAL 180352

__device__ __forceinline__ uint32_t s2u(const void* p) {
    uint32_t a;
    asm("{ .reg .u64 t; cvta.to.shared.u64 t, %1; cvt.u32.u64 %0, t; }" : "=r"(a) : "l"(p));
    return a;
}

#define LDSM4(r, a)                                                               \
    asm volatile("ldmatrix.sync.aligned.m8n8.x4.shared.b16 {%0,%1,%2,%3}, [%4];"  \
                 : "=r"((r)[0]), "=r"((r)[1]), "=r"((r)[2]), "=r"((r)[3])         \
                 : "r"(a))

__device__ __forceinline__ void mma_f32(float* d, const uint32_t* a,
                                        uint32_t b0, uint32_t b1) {
    asm volatile("mma.sync.aligned.m16n8k16.row.col.f32.f16.f16.f32 "
                 "{%0,%1,%2,%3}, {%4,%5,%6,%7}, {%8,%9}, {%0,%1,%2,%3};"
                 : "+f"(d[0]), "+f"(d[1]), "+f"(d[2]), "+f"(d[3])
                 : "r"(a[0]), "r"(a[1]), "r"(a[2]), "r"(a[3]), "r"(b0), "r"(b1));
}
__device__ __forceinline__ void mma_f16(uint32_t* d, const uint32_t* a,
                                        uint32_t b0, uint32_t b1) {
    asm volatile("mma.sync.aligned.m16n8k16.row.col.f16.f16.f16.f16 "
                 "{%0,%1}, {%2,%3,%4,%5}, {%6,%7}, {%0,%1};"
                 : "+r"(d[0]), "+r"(d[1])
                 : "r"(a[0]), "r"(a[1]), "r"(a[2]), "r"(a[3]), "r"(b0), "r"(b1));
}

__global__ void __launch_bounds__(NTHR, 1) VanillaRNN_54984171323420_kernel(
    const float* __restrict__ x,    // [2048, 512]
    const float* __restrict__ Whx,  // [256, 1]
    const float* __restrict__ Whh,  // [256, 256]
    const float* __restrict__ Wph,  // [10, 256]
    const float* __restrict__ bh,   // [256, 2048]
    const float* __restrict__ bp,   // [10, 2048]
    float* __restrict__ out)        // [2048, 10]
{
    extern __shared__ char smc[];
    const uint32_t sb = s2u(smc);
    const int tid = threadIdx.x;
    const int w = tid >> 5;          // warp 0..7 -> m rows [32w, 32w+32)
    const int l = tid & 31;
    const int lq = l >> 2;
    const int lr = (l & 3) * 2;
    const int lx = l >> 4;
    const int l7 = l & 7;
    const int m0 = 32 * w;
    const int j0 = blockIdx.x * NCOL;

    // ---------------- stage W_hi into smem (swizzled 512B rows) ----------------
    for (int idx = tid; idx < HDIM * HDIM; idx += NTHR) {
        int m = idx >> 8, k = idx & 255;
        __half hi = __float2half_rn(Whh[idx]);
        uint32_t ch = (uint32_t)(((k >> 3) ^ (m & 7)) << 4);
        *(__half*)(smc + SM_W + m * 512 + ch + (k & 7) * 2) = hi;
    }
    float xn1 = 0.0f;
    if (tid < NCOL) {
        const float* xr = x + (j0 + tid) * SEQT;
        *(float*)(smc + SM_XR + 64 + tid * 4) = xr[0];
        xn1 = xr[1];
    }
    __syncthreads();

    // ---------------- A_hi fragments -> registers (loop-invariant, 128 regs) ----
    const uint32_t rowAL0 = sb + SM_W + (uint32_t)(m0 + (l & 15)) * 512;
    const uint32_t rowAL1 = rowAL0 + 16 * 512;
    uint32_t ahi0[16][4], ahi1[16][4];
#pragma unroll
    for (int ks = 0; ks < 16; ks++) {
        const uint32_t ch = (uint32_t)(((2 * ks + lx) ^ l7) << 4);
        LDSM4(ahi0[ks], rowAL0 + ch);
        LDSM4(ahi1[ks], rowAL1 + ch);
    }
    __syncthreads();

    // ---------------- overwrite staging with W_lo * 2^8 ----------------
    for (int idx = tid; idx < HDIM * HDIM; idx += NTHR) {
        int m = idx >> 8, k = idx & 255;
        float wv = Whh[idx];
        __half hi = __float2half_rn(wv);
        __half lo = __float2half_rn((wv - __half2float(hi)) * SCALE);
        uint32_t ch = (uint32_t)(((k >> 3) ^ (m & 7)) << 4);
        *(__half*)(smc + SM_W + m * 512 + ch + (k & 7) * 2) = lo;
    }

    // ------- bias -> smem [q][tid]; Whx in regs; packed store offsets -------
    float wx[2][2];
    uint32_t boff[8];                 // per-element swizzled store offsets (u16 x2)
#pragma unroll
    for (int tm = 0; tm < 2; tm++) {
        wx[tm][0] = Whx[m0 + 16 * tm + lq];
        wx[tm][1] = Whx[m0 + 16 * tm + lq + 8];
#pragma unroll
        for (int tn = 0; tn < 2; tn++)
#pragma unroll
            for (int e = 0; e < 4; e++) {
                int m = m0 + 16 * tm + lq + ((e >> 1) ? 8 : 0);
                int n = 8 * tn + lr + (e & 1);
                int q = tm * 8 + tn * 4 + e;
                *(float*)(smc + SM_BIAS + (q * 256 + tid) * 4) = bh[m * BATCH + j0 + n];
                uint32_t off = (uint32_t)n * 512 + ((((uint32_t)m >> 3) ^ (n & 7)) << 4) + (m & 7) * 2;
                if (q & 1) boff[q >> 1] |= off << 16;
                else       boff[q >> 1] = off;
            }
    }

    // ---------------- prologue: h1 = tanh(b_h + Whx*x_0) -> buf0 ----------------
#pragma unroll
    for (int q = 0; q < 16; q++) {
        int tm = q >> 3, tn = (q >> 2) & 1, e = q & 3;
        int n = 8 * tn + lr + (e & 1);
        int mh = e >> 1;
        float bv = *(const float*)(smc + SM_BIAS + (q * 256 + tid) * 4);
        float xv = *(const float*)(smc + SM_XR + 64 + n * 4);
        float pre = bv + wx[tm][mh] * xv;
        float ev = __expf(2.0f * pre);
        float h = 1.0f - __fdividef(2.0f, ev + 1.0f);
        __half hi = __float2half_rn(h);
        __half lo = __float2half_rn((h - __half2float(hi)) * SCALE);
        uint32_t off = (boff[q >> 1] >> (16 * (q & 1))) & 0xFFFFu;
        *(__half*)(smc + SM_B + off) = hi;
        *(__half*)(smc + SM_B + 8192 + off) = lo;
    }
    if (tid < NCOL) *(float*)(smc + SM_XR + tid * 4) = xn1;  // slot0 <- x_1
    __syncthreads();

    const uint32_t rowBb = sb + SM_B + (uint32_t)(l & 15) * 512;
    const char* biasp = smc + SM_BIAS + (uint32_t)tid * 4;   // generic pointer

    // ---- first step's accumulator init (hoisted) ----
    float d32[16];
#pragma unroll
    for (int q = 0; q < 16; q++) d32[q] = *(const float*)(biasp + q * 1024);

    // ================= recurrence: 510 HMMA steps, 1 bar/step =================
#pragma unroll 2
    for (int it = 0; it < NSTEPS; it++) {
        const int p = it & 1;                 // read buf p, write buf 1-p
        float xnext = 0.0f;
        if (tid < NCOL) xnext = x[(j0 + tid) * SEQT + it + 2];

        const uint32_t rowB = rowBb + (uint32_t)p * 16384;

        uint32_t dloA[4][2], dloB[4][2];      // split f16 accum chains
#pragma unroll
        for (int q = 0; q < 4; q++) {
            dloA[q][0] = 0u; dloA[q][1] = 0u;
            dloB[q][0] = 0u; dloB[q][1] = 0u;
        }

#pragma unroll
        for (int ks = 0; ks < 16; ks++) {
            const uint32_t ch = (uint32_t)(((2 * ks + lx) ^ l7) << 4);
            uint32_t bh4[4], bl4[4], al0[4], al1[4];
            LDSM4(bh4, rowB + ch);
            LDSM4(bl4, rowB + 8192 + ch);
            LDSM4(al0, rowAL0 + ch);
            LDSM4(al1, rowAL1 + ch);
            // main pass: W_hi . h_hi  (f32 accum)
            mma_f32(&d32[0],  ahi0[ks], bh4[0], bh4[2]);
            mma_f32(&d32[4],  ahi0[ks], bh4[1], bh4[3]);
            mma_f32(&d32[8],  ahi1[ks], bh4[0], bh4[2]);
            mma_f32(&d32[12], ahi1[ks], bh4[1], bh4[3]);
            // correction passes (x 2^8), independent chains
            mma_f16(dloA[0], al0,      bh4[0], bh4[2]);
            mma_f16(dloB[0], ahi0[ks], bl4[0], bl4[2]);
            mma_f16(dloA[1], al0,      bh4[1], bh4[3]);
            mma_f16(dloB[1], ahi0[ks], bl4[1], bl4[3]);
            mma_f16(dloA[2], al1,      bh4[0], bh4[2]);
            mma_f16(dloB[2], ahi1[ks], bl4[0], bl4[2]);
            mma_f16(dloA[3], al1,      bh4[1], bh4[3]);
            mma_f16(dloB[3], ahi1[ks], bl4[1], bl4[3]);
        }

        // ---- epilogue: h = tanh(d32 + dlo*2^-8 + Whx*x) -> buf 1-p ----
        const uint32_t xsl = (uint32_t)(SM_XR + p * 64);
        const uint32_t bufw = (uint32_t)(SM_B + (1 - p) * 16384);

        float pre[16];
#pragma unroll
        for (int g = 0; g < 4; g++) {
            float2 a01 = __half22float2(*(__half2*)&dloA[g][0]);
            float2 a23 = __half22float2(*(__half2*)&dloA[g][1]);
            float2 b01 = __half22float2(*(__half2*)&dloB[g][0]);
            float2 b23 = __half22float2(*(__half2*)&dloB[g][1]);
            float lov[4] = {a01.x + b01.x, a01.y + b01.y, a23.x + b23.x, a23.y + b23.y};
            int tm = g >> 1, tn = g & 1;
#pragma unroll
            for (int e = 0; e < 4; e++) {
                int q = tm * 8 + tn * 4 + e;
                int n = 8 * tn + lr + (e & 1);
                float xv = *(const float*)(smc + xsl + n * 4);
                pre[q] = fmaf(wx[tm][e >> 1], xv, fmaf(lov[e], INVSCALE, d32[q]));
            }
        }
        float ev[16];
#pragma unroll
        for (int q = 0; q < 16; q++) ev[q] = __expf(2.0f * pre[q]);
        float hv[16];
#pragma unroll
        for (int q = 0; q < 16; q++) hv[q] = 1.0f - __fdividef(2.0f, ev[q] + 1.0f);
#pragma unroll
        for (int q = 0; q < 16; q++) {
            __half hi = __float2half_rn(hv[q]);
            __half lo = __float2half_rn((hv[q] - __half2float(hi)) * SCALE);
            uint32_t off = (boff[q >> 1] >> (16 * (q & 1))) & 0xFFFFu;
            *(__half*)(smc + bufw + off) = hi;
            *(__half*)(smc + bufw + 8192 + off) = lo;
        }
        if (tid < NCOL) *(float*)(smc + SM_XR + (1 - p) * 64 + tid * 4) = xnext;

        // next step's accumulator init before the barrier (off critical path)
#pragma unroll
        for (int q = 0; q < 16; q++) d32[q] = *(const float*)(biasp + q * 1024);
        __syncthreads();
    }

    // ================= projection: out = Wph @ h + bp =================
    // final h lives in buf0 (it=509 wrote buf 1-p = 0)
    if (tid < 10 * NCOL) {
        const int c = tid >> 4, j = tid & 15;
        float s = bp[c * BATCH + j0 + j];
        const float* wr = Wph + c * HDIM;
#pragma unroll 8
        for (int k = 0; k < HDIM; k++) {
            uint32_t off = (uint32_t)j * 512 + ((((uint32_t)k >> 3) ^ (j & 7)) << 4) + (k & 7) * 2;
            float hvv = __half2float(*(__half*)(smc + SM_B + off)) +
                        __half2float(*(__half*)(smc + SM_B + 8192 + off)) * INVSCALE;
            s = fmaf(wr[k], hvv, s);
        }
        out[(j0 + j) * 10 + c] = s;
    }
}

extern "C" void kernel_launch(void* const* d_in, const int* in_sizes, int n_in,
                              void* d_out, int out_size) {
    const float* x   = (const float*)d_in[0];
    const float* Whx = (const float*)d_in[1];
    const float* Whh = (const float*)d_in[2];
    const float* Wph = (const float*)d_in[3];
    const float* bh  = (const float*)d_in[4];
    const float* bp  = (const float*)d_in[5];
    float* out = (float*)d_out;

    cudaFuncSetAttribute(VanillaRNN_54984171323420_kernel,
                         cudaFuncAttributeMaxDynamicSharedMemorySize, SM_TOTAL);
    VanillaRNN_54984171323420_kernel<<<NBLK, NTHR, SM_TOTAL>>>(
        x, Whx, Whh, Wph, bh, bp, out);
}